// round 3
// baseline (speedup 1.0000x reference)
#include <cuda_runtime.h>
#include <cuda_bf16.h>
#include <cstdint>

// Problem constants
#define BATCH 2
#define SEQ   2048
#define EMB   1024
#define NH    16
#define DH    64
#define WIN   128

// Scratch (static __device__ globals -- allocation-free)
__device__ float g_Q[BATCH * NH * SEQ * DH];   // [B,H,S,dh]
__device__ float g_K[BATCH * NH * SEQ * DH];
__device__ float g_V[BATCH * NH * SEQ * DH];
__device__ float g_ctx[BATCH * SEQ * EMB];     // [B,S,D]

// ---------------------------------------------------------------------------
// GEMM: C = A[M,K] * W[N,K]^T + bias[N]   (both K-major, "NT")
// MODE 0: C row-major [M,N]
// MODE 1: scatter into [B,H,S,dh] head-major layout (for Q/K/V)
// Tile 64x64, BK=16, 256 threads, 4x4 per thread.
// ---------------------------------------------------------------------------
template <int MODE>
__global__ void __launch_bounds__(256, 4)
gemm_nt(const float* __restrict__ A, const float* __restrict__ W,
        const float* __restrict__ bias, float* __restrict__ C,
        int M, int N, int K)
{
    __shared__ float As[16][68];
    __shared__ float Bs[16][68];

    const int tid = threadIdx.x;
    const int tx = tid & 15;        // n micro index
    const int ty = tid >> 4;        // m micro index
    const int m0 = blockIdx.y * 64;
    const int n0 = blockIdx.x * 64;

    const float* Ap = A + (size_t)m0 * K;
    const float* Wp = W + (size_t)n0 * K;

    const int lrow = tid >> 2;          // 0..63
    const int lc4  = (tid & 3) << 2;    // 0,4,8,12

    float acc[4][4];
#pragma unroll
    for (int i = 0; i < 4; i++)
#pragma unroll
        for (int j = 0; j < 4; j++) acc[i][j] = 0.f;

    for (int k0 = 0; k0 < K; k0 += 16) {
        float4 a4 = *(const float4*)(Ap + (size_t)lrow * K + k0 + lc4);
        float4 b4 = *(const float4*)(Wp + (size_t)lrow * K + k0 + lc4);
        As[lc4 + 0][lrow] = a4.x; As[lc4 + 1][lrow] = a4.y;
        As[lc4 + 2][lrow] = a4.z; As[lc4 + 3][lrow] = a4.w;
        Bs[lc4 + 0][lrow] = b4.x; Bs[lc4 + 1][lrow] = b4.y;
        Bs[lc4 + 2][lrow] = b4.z; Bs[lc4 + 3][lrow] = b4.w;
        __syncthreads();
#pragma unroll
        for (int kk = 0; kk < 16; kk++) {
            float4 av = *(const float4*)&As[kk][ty << 2];
            float4 bv = *(const float4*)&Bs[kk][tx << 2];
            acc[0][0] += av.x * bv.x; acc[0][1] += av.x * bv.y;
            acc[0][2] += av.x * bv.z; acc[0][3] += av.x * bv.w;
            acc[1][0] += av.y * bv.x; acc[1][1] += av.y * bv.y;
            acc[1][2] += av.y * bv.z; acc[1][3] += av.y * bv.w;
            acc[2][0] += av.z * bv.x; acc[2][1] += av.z * bv.y;
            acc[2][2] += av.z * bv.z; acc[2][3] += av.z * bv.w;
            acc[3][0] += av.w * bv.x; acc[3][1] += av.w * bv.y;
            acc[3][2] += av.w * bv.z; acc[3][3] += av.w * bv.w;
        }
        __syncthreads();
    }

#pragma unroll
    for (int i = 0; i < 4; i++) {
        const int m = m0 + (ty << 2) + i;
#pragma unroll
        for (int j = 0; j < 4; j++) {
            const int n = n0 + (tx << 2) + j;
            const float val = acc[i][j] + bias[n];
            if (MODE == 0) {
                C[(size_t)m * N + n] = val;
            } else {
                const int b = m >> 11;       // SEQ = 2048
                const int s = m & 2047;
                const int h = n >> 6;        // DH = 64
                const int d = n & 63;
                C[(((size_t)(b * NH + h)) * SEQ + s) * DH + d] = val;
            }
        }
    }
}

// ---------------------------------------------------------------------------
// Banded attention: one CTA = 64 queries of one (b,h).
// Key window of 320 keys, full score tile in smem, exact softmax,
// writes ctx ([B,S,H,dh] == [B,S,D]) and attn band rows.
// ---------------------------------------------------------------------------
__global__ void __launch_bounds__(256, 1)
attn_kernel(const float* __restrict__ Q, const float* __restrict__ K,
            const float* __restrict__ V, float* __restrict__ ctx,
            float* __restrict__ attn, int writeAttn)
{
    constexpr int BQ = 64;
    constexpr int KW = 2 * WIN + BQ;   // 320
    constexpr int PS = KW + 1;         // 321 (score row stride)
    constexpr int LD = 68;             // padded tile stride

    extern __shared__ float sm[];
    float* Qs = sm;                    // [DH][LD]  (d-major)
    float* Ts = sm + DH * LD;          // K phase: [DH][LD] d-major; V phase: [64][LD] k-major
    float* Ss = sm + 2 * DH * LD;      // [BQ][PS]

    const int tid = threadIdx.x;
    const int tx = tid & 15;
    const int ty = tid >> 4;
    const int qt = blockIdx.x, h = blockIdx.y, b = blockIdx.z;
    const int q0 = qt * BQ;
    const int kstart = q0 - WIN;

    const float* Qb = Q + ((size_t)(b * NH + h) * SEQ + q0) * DH;
    const float* Kb = K + (size_t)(b * NH + h) * SEQ * DH;
    const float* Vb = V + (size_t)(b * NH + h) * SEQ * DH;

    // Load Q tile transposed: Qs[d][q]
#pragma unroll
    for (int i = 0; i < 4; i++) {
        const int idx = tid + i * 256;
        const int row = idx >> 4;
        const int c4 = (idx & 15) << 2;
        float4 v = *(const float4*)(Qb + row * DH + c4);
        Qs[(c4 + 0) * LD + row] = v.x;
        Qs[(c4 + 1) * LD + row] = v.y;
        Qs[(c4 + 2) * LD + row] = v.z;
        Qs[(c4 + 3) * LD + row] = v.w;
    }
    __syncthreads();

    // ---- Phase 1: scores ----
    for (int t = 0; t < 5; t++) {
        const int kg0 = kstart + t * 64;
#pragma unroll
        for (int i = 0; i < 4; i++) {
            const int idx = tid + i * 256;
            const int row = idx >> 4;
            const int c4 = (idx & 15) << 2;
            const int kr = kg0 + row;
            float4 v = make_float4(0.f, 0.f, 0.f, 0.f);
            if (kr >= 0 && kr < SEQ)
                v = *(const float4*)(Kb + (size_t)kr * DH + c4);
            Ts[(c4 + 0) * LD + row] = v.x;
            Ts[(c4 + 1) * LD + row] = v.y;
            Ts[(c4 + 2) * LD + row] = v.z;
            Ts[(c4 + 3) * LD + row] = v.w;
        }
        __syncthreads();

        float acc[4][4];
#pragma unroll
        for (int i = 0; i < 4; i++)
#pragma unroll
            for (int j = 0; j < 4; j++) acc[i][j] = 0.f;

#pragma unroll 8
        for (int d = 0; d < DH; d++) {
            float4 av = *(const float4*)&Qs[d * LD + (ty << 2)];
            float4 bv = *(const float4*)&Ts[d * LD + (tx << 2)];
            acc[0][0] += av.x * bv.x; acc[0][1] += av.x * bv.y;
            acc[0][2] += av.x * bv.z; acc[0][3] += av.x * bv.w;
            acc[1][0] += av.y * bv.x; acc[1][1] += av.y * bv.y;
            acc[1][2] += av.y * bv.z; acc[1][3] += av.y * bv.w;
            acc[2][0] += av.z * bv.x; acc[2][1] += av.z * bv.y;
            acc[2][2] += av.z * bv.z; acc[2][3] += av.z * bv.w;
            acc[3][0] += av.w * bv.x; acc[3][1] += av.w * bv.y;
            acc[3][2] += av.w * bv.z; acc[3][3] += av.w * bv.w;
        }
#pragma unroll
        for (int i = 0; i < 4; i++)
#pragma unroll
            for (int j = 0; j < 4; j++)
                Ss[((ty << 2) + i) * PS + t * 64 + (tx << 2) + j] = acc[i][j] * 0.125f;
        __syncthreads();
    }

    // ---- Phase 2: softmax per query row (one warp owns 8 rows) ----
    const int warp = tid >> 5, lane = tid & 31;
    for (int r = 0; r < 8; r++) {
        const int iq = warp * 8 + r;
        const int q = q0 + iq;
        int jlo = iq;
        if (kstart + jlo < 0) jlo = -kstart;
        int jhi = iq + 2 * WIN;
        if (kstart + jhi > SEQ - 1) jhi = SEQ - 1 - kstart;
        float* row = &Ss[iq * PS];

        for (int j = lane; j < jlo; j += 32) row[j] = 0.f;
        for (int j = jhi + 1 + lane; j < KW; j += 32) row[j] = 0.f;

        float mx = -1e30f;
        for (int j = jlo + lane; j <= jhi; j += 32) mx = fmaxf(mx, row[j]);
#pragma unroll
        for (int o = 16; o; o >>= 1) mx = fmaxf(mx, __shfl_xor_sync(0xffffffffu, mx, o));

        float ssum = 0.f;
        for (int j = jlo + lane; j <= jhi; j += 32) {
            float e = __expf(row[j] - mx);
            row[j] = e;
            ssum += e;
        }
#pragma unroll
        for (int o = 16; o; o >>= 1) ssum += __shfl_xor_sync(0xffffffffu, ssum, o);
        const float inv = 1.f / ssum;

        if (writeAttn) {
            float* arow = attn + ((size_t)(b * NH + h) * SEQ + q) * SEQ;
            for (int j = jlo + lane; j <= jhi; j += 32) {
                float p = row[j] * inv;
                row[j] = p;
                arow[kstart + j] = p;
            }
        } else {
            for (int j = jlo + lane; j <= jhi; j += 32) row[j] *= inv;
        }
    }
    __syncthreads();

    // ---- Phase 3: ctx = P @ V ----
    float cacc[4][4];
#pragma unroll
    for (int i = 0; i < 4; i++)
#pragma unroll
        for (int j = 0; j < 4; j++) cacc[i][j] = 0.f;

    for (int t = 0; t < 5; t++) {
        const int kg0 = kstart + t * 64;
#pragma unroll
        for (int i = 0; i < 4; i++) {
            const int idx = tid + i * 256;
            const int row = idx >> 4;
            const int c4 = (idx & 15) << 2;
            const int kr = kg0 + row;
            float4 v = make_float4(0.f, 0.f, 0.f, 0.f);
            if (kr >= 0 && kr < SEQ)
                v = *(const float4*)(Vb + (size_t)kr * DH + c4);
            *(float4*)&Ts[row * LD + c4] = v;   // Vs[k][d]
        }
        __syncthreads();

#pragma unroll 8
        for (int kk = 0; kk < 64; kk++) {
            float4 bv = *(const float4*)&Ts[kk * LD + (tx << 2)];
            const int col = t * 64 + kk;
            float a0 = Ss[((ty << 2) + 0) * PS + col];
            float a1 = Ss[((ty << 2) + 1) * PS + col];
            float a2 = Ss[((ty << 2) + 2) * PS + col];
            float a3 = Ss[((ty << 2) + 3) * PS + col];
            cacc[0][0] += a0 * bv.x; cacc[0][1] += a0 * bv.y;
            cacc[0][2] += a0 * bv.z; cacc[0][3] += a0 * bv.w;
            cacc[1][0] += a1 * bv.x; cacc[1][1] += a1 * bv.y;
            cacc[1][2] += a1 * bv.z; cacc[1][3] += a1 * bv.w;
            cacc[2][0] += a2 * bv.x; cacc[2][1] += a2 * bv.y;
            cacc[2][2] += a2 * bv.z; cacc[2][3] += a2 * bv.w;
            cacc[3][0] += a3 * bv.x; cacc[3][1] += a3 * bv.y;
            cacc[3][2] += a3 * bv.z; cacc[3][3] += a3 * bv.w;
        }
        __syncthreads();
    }

#pragma unroll
    for (int i = 0; i < 4; i++) {
        const int q = q0 + (ty << 2) + i;
        float4 val = make_float4(cacc[i][0], cacc[i][1], cacc[i][2], cacc[i][3]);
        *(float4*)(ctx + (((size_t)b * SEQ + q) * NH + h) * DH + (tx << 2)) = val;
    }
}

// ---------------------------------------------------------------------------
extern "C" void kernel_launch(void* const* d_in, const int* in_sizes, int n_in,
                              void* d_out, int out_size)
{
    const float* x  = (const float*)d_in[0];
    const float* Wq = (const float*)d_in[1];
    const float* bq = (const float*)d_in[2];
    const float* Wk = (const float*)d_in[3];
    const float* bk = (const float*)d_in[4];
    const float* Wv = (const float*)d_in[5];
    const float* bv = (const float*)d_in[6];
    const float* Wo = (const float*)d_in[7];
    const float* bo = (const float*)d_in[8];
    float* out = (float*)d_out;

    float *Qp, *Kp, *Vp, *Cp;
    cudaGetSymbolAddress((void**)&Qp, g_Q);
    cudaGetSymbolAddress((void**)&Kp, g_K);
    cudaGetSymbolAddress((void**)&Vp, g_V);
    cudaGetSymbolAddress((void**)&Cp, g_ctx);

    const size_t OUT_ELEMS  = (size_t)BATCH * SEQ * EMB;                 // 4,194,304
    const size_t ATTN_ELEMS = (size_t)BATCH * NH * SEQ * SEQ;            // 134,217,728
    const int writeAttn = ((size_t)out_size >= OUT_ELEMS + ATTN_ELEMS) ? 1 : 0;
    float* attn_ptr = out + OUT_ELEMS;

    const int M = BATCH * SEQ;   // 4096

    dim3 gblk(256);
    dim3 ggrid(EMB / 64, M / 64);

    // Q/K/V projections into head-major scratch
    gemm_nt<1><<<ggrid, gblk>>>(x, Wq, bq, Qp, M, EMB, EMB);
    gemm_nt<1><<<ggrid, gblk>>>(x, Wk, bk, Kp, M, EMB, EMB);
    gemm_nt<1><<<ggrid, gblk>>>(x, Wv, bv, Vp, M, EMB, EMB);

    // Zero the attn output region (masked softmax entries are exactly 0)
    if (writeAttn)
        cudaMemsetAsync(attn_ptr, 0, ATTN_ELEMS * sizeof(float), 0);

    // Banded attention
    constexpr int SMEM = (2 * 64 * 68 + 64 * 321) * (int)sizeof(float);  // 116,992 B
    cudaFuncSetAttribute(attn_kernel, cudaFuncAttributeMaxDynamicSharedMemorySize, SMEM);
    attn_kernel<<<dim3(SEQ / 64, NH, BATCH), 256, SMEM>>>(Qp, Kp, Vp, Cp, attn_ptr, writeAttn);

    // Output projection
    gemm_nt<0><<<ggrid, gblk>>>(Cp, Wo, bo, out, M, EMB, EMB);
}

// round 4
// speedup vs baseline: 1.0002x; 1.0002x over previous
#include <cuda_runtime.h>
#include <cuda_bf16.h>
#include <cstdint>

// Problem constants
#define BATCH 2
#define SEQ   2048
#define EMB   1024
#define NH    16
#define DH    64
#define WIN   128

// Scratch (static __device__ globals -- allocation-free)
__device__ float g_Q[BATCH * NH * SEQ * DH];   // [B,H,S,dh]
__device__ float g_K[BATCH * NH * SEQ * DH];
__device__ float g_V[BATCH * NH * SEQ * DH];
__device__ float g_ctx[BATCH * SEQ * EMB];     // [B,S,D]

// ---------------------------------------------------------------------------
// GEMM: C = A[M,K] * W[N,K]^T + bias[N]   (both K-major, "NT")
// MODE 0: C row-major [M,N]
// MODE 1: scatter into [B,H,S,dh] head-major layout (for Q/K/V)
// Tile 64x64, BK=16, 256 threads, 4x4 per thread.
// ---------------------------------------------------------------------------
template <int MODE>
__global__ void __launch_bounds__(256, 4)
gemm_nt(const float* __restrict__ A, const float* __restrict__ W,
        const float* __restrict__ bias, float* __restrict__ C,
        int M, int N, int K)
{
    __shared__ float As[16][68];
    __shared__ float Bs[16][68];

    const int tid = threadIdx.x;
    const int tx = tid & 15;        // n micro index
    const int ty = tid >> 4;        // m micro index
    const int m0 = blockIdx.y * 64;
    const int n0 = blockIdx.x * 64;

    const float* Ap = A + (size_t)m0 * K;
    const float* Wp = W + (size_t)n0 * K;

    const int lrow = tid >> 2;          // 0..63
    const int lc4  = (tid & 3) << 2;    // 0,4,8,12

    float acc[4][4];
#pragma unroll
    for (int i = 0; i < 4; i++)
#pragma unroll
        for (int j = 0; j < 4; j++) acc[i][j] = 0.f;

    for (int k0 = 0; k0 < K; k0 += 16) {
        float4 a4 = *(const float4*)(Ap + (size_t)lrow * K + k0 + lc4);
        float4 b4 = *(const float4*)(Wp + (size_t)lrow * K + k0 + lc4);
        As[lc4 + 0][lrow] = a4.x; As[lc4 + 1][lrow] = a4.y;
        As[lc4 + 2][lrow] = a4.z; As[lc4 + 3][lrow] = a4.w;
        Bs[lc4 + 0][lrow] = b4.x; Bs[lc4 + 1][lrow] = b4.y;
        Bs[lc4 + 2][lrow] = b4.z; Bs[lc4 + 3][lrow] = b4.w;
        __syncthreads();
#pragma unroll
        for (int kk = 0; kk < 16; kk++) {
            float4 av = *(const float4*)&As[kk][ty << 2];
            float4 bv = *(const float4*)&Bs[kk][tx << 2];
            acc[0][0] += av.x * bv.x; acc[0][1] += av.x * bv.y;
            acc[0][2] += av.x * bv.z; acc[0][3] += av.x * bv.w;
            acc[1][0] += av.y * bv.x; acc[1][1] += av.y * bv.y;
            acc[1][2] += av.y * bv.z; acc[1][3] += av.y * bv.w;
            acc[2][0] += av.z * bv.x; acc[2][1] += av.z * bv.y;
            acc[2][2] += av.z * bv.z; acc[2][3] += av.z * bv.w;
            acc[3][0] += av.w * bv.x; acc[3][1] += av.w * bv.y;
            acc[3][2] += av.w * bv.z; acc[3][3] += av.w * bv.w;
        }
        __syncthreads();
    }

#pragma unroll
    for (int i = 0; i < 4; i++) {
        const int m = m0 + (ty << 2) + i;
#pragma unroll
        for (int j = 0; j < 4; j++) {
            const int n = n0 + (tx << 2) + j;
            const float val = acc[i][j] + bias[n];
            if (MODE == 0) {
                C[(size_t)m * N + n] = val;
            } else {
                const int b = m >> 11;       // SEQ = 2048
                const int s = m & 2047;
                const int h = n >> 6;        // DH = 64
                const int d = n & 63;
                C[(((size_t)(b * NH + h)) * SEQ + s) * DH + d] = val;
            }
        }
    }
}

// ---------------------------------------------------------------------------
// Banded attention: one CTA = 64 queries of one (b,h).
// Key window of 320 keys, full score tile in smem, exact softmax,
// writes ctx ([B,S,H,dh] == [B,S,D]) and attn band rows.
// ---------------------------------------------------------------------------
__global__ void __launch_bounds__(256, 1)
attn_kernel(const float* __restrict__ Q, const float* __restrict__ K,
            const float* __restrict__ V, float* __restrict__ ctx,
            float* __restrict__ attn, int writeAttn)
{
    constexpr int BQ = 64;
    constexpr int KW = 2 * WIN + BQ;   // 320
    constexpr int PS = KW + 1;         // 321 (score row stride)
    constexpr int LD = 68;             // padded tile stride

    extern __shared__ float sm[];
    float* Qs = sm;                    // [DH][LD]  (d-major)
    float* Ts = sm + DH * LD;          // K phase: [DH][LD] d-major; V phase: [64][LD] k-major
    float* Ss = sm + 2 * DH * LD;      // [BQ][PS]

    const int tid = threadIdx.x;
    const int tx = tid & 15;
    const int ty = tid >> 4;
    const int qt = blockIdx.x, h = blockIdx.y, b = blockIdx.z;
    const int q0 = qt * BQ;
    const int kstart = q0 - WIN;

    const float* Qb = Q + ((size_t)(b * NH + h) * SEQ + q0) * DH;
    const float* Kb = K + (size_t)(b * NH + h) * SEQ * DH;
    const float* Vb = V + (size_t)(b * NH + h) * SEQ * DH;

    // Load Q tile transposed: Qs[d][q]
#pragma unroll
    for (int i = 0; i < 4; i++) {
        const int idx = tid + i * 256;
        const int row = idx >> 4;
        const int c4 = (idx & 15) << 2;
        float4 v = *(const float4*)(Qb + row * DH + c4);
        Qs[(c4 + 0) * LD + row] = v.x;
        Qs[(c4 + 1) * LD + row] = v.y;
        Qs[(c4 + 2) * LD + row] = v.z;
        Qs[(c4 + 3) * LD + row] = v.w;
    }
    __syncthreads();

    // ---- Phase 1: scores ----
    for (int t = 0; t < 5; t++) {
        const int kg0 = kstart + t * 64;
#pragma unroll
        for (int i = 0; i < 4; i++) {
            const int idx = tid + i * 256;
            const int row = idx >> 4;
            const int c4 = (idx & 15) << 2;
            const int kr = kg0 + row;
            float4 v = make_float4(0.f, 0.f, 0.f, 0.f);
            if (kr >= 0 && kr < SEQ)
                v = *(const float4*)(Kb + (size_t)kr * DH + c4);
            Ts[(c4 + 0) * LD + row] = v.x;
            Ts[(c4 + 1) * LD + row] = v.y;
            Ts[(c4 + 2) * LD + row] = v.z;
            Ts[(c4 + 3) * LD + row] = v.w;
        }
        __syncthreads();

        float acc[4][4];
#pragma unroll
        for (int i = 0; i < 4; i++)
#pragma unroll
            for (int j = 0; j < 4; j++) acc[i][j] = 0.f;

#pragma unroll 8
        for (int d = 0; d < DH; d++) {
            float4 av = *(const float4*)&Qs[d * LD + (ty << 2)];
            float4 bv = *(const float4*)&Ts[d * LD + (tx << 2)];
            acc[0][0] += av.x * bv.x; acc[0][1] += av.x * bv.y;
            acc[0][2] += av.x * bv.z; acc[0][3] += av.x * bv.w;
            acc[1][0] += av.y * bv.x; acc[1][1] += av.y * bv.y;
            acc[1][2] += av.y * bv.z; acc[1][3] += av.y * bv.w;
            acc[2][0] += av.z * bv.x; acc[2][1] += av.z * bv.y;
            acc[2][2] += av.z * bv.z; acc[2][3] += av.z * bv.w;
            acc[3][0] += av.w * bv.x; acc[3][1] += av.w * bv.y;
            acc[3][2] += av.w * bv.z; acc[3][3] += av.w * bv.w;
        }
#pragma unroll
        for (int i = 0; i < 4; i++)
#pragma unroll
            for (int j = 0; j < 4; j++)
                Ss[((ty << 2) + i) * PS + t * 64 + (tx << 2) + j] = acc[i][j] * 0.125f;
        __syncthreads();
    }

    // ---- Phase 2: softmax per query row (one warp owns 8 rows) ----
    const int warp = tid >> 5, lane = tid & 31;
    for (int r = 0; r < 8; r++) {
        const int iq = warp * 8 + r;
        const int q = q0 + iq;
        int jlo = iq;
        if (kstart + jlo < 0) jlo = -kstart;
        int jhi = iq + 2 * WIN;
        if (kstart + jhi > SEQ - 1) jhi = SEQ - 1 - kstart;
        float* row = &Ss[iq * PS];

        for (int j = lane; j < jlo; j += 32) row[j] = 0.f;
        for (int j = jhi + 1 + lane; j < KW; j += 32) row[j] = 0.f;

        float mx = -1e30f;
        for (int j = jlo + lane; j <= jhi; j += 32) mx = fmaxf(mx, row[j]);
#pragma unroll
        for (int o = 16; o; o >>= 1) mx = fmaxf(mx, __shfl_xor_sync(0xffffffffu, mx, o));

        float ssum = 0.f;
        for (int j = jlo + lane; j <= jhi; j += 32) {
            float e = __expf(row[j] - mx);
            row[j] = e;
            ssum += e;
        }
#pragma unroll
        for (int o = 16; o; o >>= 1) ssum += __shfl_xor_sync(0xffffffffu, ssum, o);
        const float inv = 1.f / ssum;

        if (writeAttn) {
            float* arow = attn + ((size_t)(b * NH + h) * SEQ + q) * SEQ;
            for (int j = jlo + lane; j <= jhi; j += 32) {
                float p = row[j] * inv;
                row[j] = p;
                arow[kstart + j] = p;
            }
        } else {
            for (int j = jlo + lane; j <= jhi; j += 32) row[j] *= inv;
        }
    }
    __syncthreads();

    // ---- Phase 3: ctx = P @ V ----
    float cacc[4][4];
#pragma unroll
    for (int i = 0; i < 4; i++)
#pragma unroll
        for (int j = 0; j < 4; j++) cacc[i][j] = 0.f;

    for (int t = 0; t < 5; t++) {
        const int kg0 = kstart + t * 64;
#pragma unroll
        for (int i = 0; i < 4; i++) {
            const int idx = tid + i * 256;
            const int row = idx >> 4;
            const int c4 = (idx & 15) << 2;
            const int kr = kg0 + row;
            float4 v = make_float4(0.f, 0.f, 0.f, 0.f);
            if (kr >= 0 && kr < SEQ)
                v = *(const float4*)(Vb + (size_t)kr * DH + c4);
            *(float4*)&Ts[row * LD + c4] = v;   // Vs[k][d]
        }
        __syncthreads();

#pragma unroll 8
        for (int kk = 0; kk < 64; kk++) {
            float4 bv = *(const float4*)&Ts[kk * LD + (tx << 2)];
            const int col = t * 64 + kk;
            float a0 = Ss[((ty << 2) + 0) * PS + col];
            float a1 = Ss[((ty << 2) + 1) * PS + col];
            float a2 = Ss[((ty << 2) + 2) * PS + col];
            float a3 = Ss[((ty << 2) + 3) * PS + col];
            cacc[0][0] += a0 * bv.x; cacc[0][1] += a0 * bv.y;
            cacc[0][2] += a0 * bv.z; cacc[0][3] += a0 * bv.w;
            cacc[1][0] += a1 * bv.x; cacc[1][1] += a1 * bv.y;
            cacc[1][2] += a1 * bv.z; cacc[1][3] += a1 * bv.w;
            cacc[2][0] += a2 * bv.x; cacc[2][1] += a2 * bv.y;
            cacc[2][2] += a2 * bv.z; cacc[2][3] += a2 * bv.w;
            cacc[3][0] += a3 * bv.x; cacc[3][1] += a3 * bv.y;
            cacc[3][2] += a3 * bv.z; cacc[3][3] += a3 * bv.w;
        }
        __syncthreads();
    }

#pragma unroll
    for (int i = 0; i < 4; i++) {
        const int q = q0 + (ty << 2) + i;
        float4 val = make_float4(cacc[i][0], cacc[i][1], cacc[i][2], cacc[i][3]);
        *(float4*)(ctx + (((size_t)b * SEQ + q) * NH + h) * DH + (tx << 2)) = val;
    }
}

// ---------------------------------------------------------------------------
extern "C" void kernel_launch(void* const* d_in, const int* in_sizes, int n_in,
                              void* d_out, int out_size)
{
    const float* x  = (const float*)d_in[0];
    const float* Wq = (const float*)d_in[1];
    const float* bq = (const float*)d_in[2];
    const float* Wk = (const float*)d_in[3];
    const float* bk = (const float*)d_in[4];
    const float* Wv = (const float*)d_in[5];
    const float* bv = (const float*)d_in[6];
    const float* Wo = (const float*)d_in[7];
    const float* bo = (const float*)d_in[8];
    float* out = (float*)d_out;

    float *Qp, *Kp, *Vp, *Cp;
    cudaGetSymbolAddress((void**)&Qp, g_Q);
    cudaGetSymbolAddress((void**)&Kp, g_K);
    cudaGetSymbolAddress((void**)&Vp, g_V);
    cudaGetSymbolAddress((void**)&Cp, g_ctx);

    const size_t OUT_ELEMS  = (size_t)BATCH * SEQ * EMB;                 // 4,194,304
    const size_t ATTN_ELEMS = (size_t)BATCH * NH * SEQ * SEQ;            // 134,217,728
    const int writeAttn = ((size_t)out_size >= OUT_ELEMS + ATTN_ELEMS) ? 1 : 0;
    float* attn_ptr = out + OUT_ELEMS;

    const int M = BATCH * SEQ;   // 4096

    dim3 gblk(256);
    dim3 ggrid(EMB / 64, M / 64);

    // Q/K/V projections into head-major scratch
    gemm_nt<1><<<ggrid, gblk>>>(x, Wq, bq, Qp, M, EMB, EMB);
    gemm_nt<1><<<ggrid, gblk>>>(x, Wk, bk, Kp, M, EMB, EMB);
    gemm_nt<1><<<ggrid, gblk>>>(x, Wv, bv, Vp, M, EMB, EMB);

    // Zero the attn output region (masked softmax entries are exactly 0)
    if (writeAttn)
        cudaMemsetAsync(attn_ptr, 0, ATTN_ELEMS * sizeof(float), 0);

    // Banded attention
    constexpr int SMEM = (2 * 64 * 68 + 64 * 321) * (int)sizeof(float);  // 116,992 B
    cudaFuncSetAttribute(attn_kernel, cudaFuncAttributeMaxDynamicSharedMemorySize, SMEM);
    attn_kernel<<<dim3(SEQ / 64, NH, BATCH), 256, SMEM>>>(Qp, Kp, Vp, Cp, attn_ptr, writeAttn);

    // Output projection
    gemm_nt<0><<<ggrid, gblk>>>(Cp, Wo, bo, out, M, EMB, EMB);
}

// round 14
// speedup vs baseline: 1.8670x; 1.8667x over previous
#include <cuda_runtime.h>
#include <cuda_bf16.h>
#include <cstdint>

// Problem constants
#define BATCH 2
#define SEQ   2048
#define EMB   1024
#define NH    16
#define DH    64
#define WIN   128

// ---------------------------------------------------------------------------
// Scratch (static __device__ globals -- allocation-free)
// ---------------------------------------------------------------------------
__device__ float g_Q[BATCH * NH * SEQ * DH];   // [B,H,S,dh]
__device__ float g_K[BATCH * NH * SEQ * DH];
__device__ float g_V[BATCH * NH * SEQ * DH];
__device__ float g_ctx[BATCH * SEQ * EMB];     // [B,S,D]

__device__ __nv_bfloat16 g_xhi[BATCH * SEQ * EMB];
__device__ __nv_bfloat16 g_xlo[BATCH * SEQ * EMB];
__device__ __nv_bfloat16 g_whi[4 * EMB * EMB];   // Wq,Wk,Wv,Wo hi parts
__device__ __nv_bfloat16 g_wlo[4 * EMB * EMB];
__device__ __nv_bfloat16 g_chi[BATCH * SEQ * EMB];
__device__ __nv_bfloat16 g_clo[BATCH * SEQ * EMB];

// ---------------------------------------------------------------------------
// Helpers (all plain-target PTX: ldmatrix / mma.sync / cp.async)
// ---------------------------------------------------------------------------
__device__ __forceinline__ uint32_t smem_u32(const void* p) {
    uint32_t a;
    asm("{ .reg .u64 t; cvta.to.shared.u64 t, %1; cvt.u32.u64 %0, t; }"
        : "=r"(a) : "l"(p));
    return a;
}

__device__ __forceinline__ void cp_async16(uint32_t dst, const void* src) {
    asm volatile("cp.async.cg.shared.global [%0], [%1], 16;\n"
                 :: "r"(dst), "l"(src));
}

__device__ __forceinline__ void ldsm_x4(uint32_t addr, uint32_t* r) {
    asm volatile("ldmatrix.sync.aligned.m8n8.x4.shared.b16 {%0,%1,%2,%3}, [%4];"
                 : "=r"(r[0]), "=r"(r[1]), "=r"(r[2]), "=r"(r[3]) : "r"(addr));
}

__device__ __forceinline__ void ldsm_x2(uint32_t addr, uint32_t* r) {
    asm volatile("ldmatrix.sync.aligned.m8n8.x2.shared.b16 {%0,%1}, [%2];"
                 : "=r"(r[0]), "=r"(r[1]) : "r"(addr));
}

__device__ __forceinline__ void mma16816(float* c, const uint32_t* a, const uint32_t* b) {
    asm volatile(
        "mma.sync.aligned.m16n8k16.row.col.f32.bf16.bf16.f32 "
        "{%0,%1,%2,%3}, {%4,%5,%6,%7}, {%8,%9}, {%0,%1,%2,%3};\n"
        : "+f"(c[0]), "+f"(c[1]), "+f"(c[2]), "+f"(c[3])
        : "r"(a[0]), "r"(a[1]), "r"(a[2]), "r"(a[3]), "r"(b[0]), "r"(b[1]));
}

// ---------------------------------------------------------------------------
// fp32 -> (hi, lo) bf16 split
// ---------------------------------------------------------------------------
__global__ void __launch_bounds__(256)
split_bf16(const float* __restrict__ in, __nv_bfloat16* __restrict__ hi,
           __nv_bfloat16* __restrict__ lo, int n4)
{
    int i = blockIdx.x * blockDim.x + threadIdx.x;
    if (i >= n4) return;
    float4 v = *(const float4*)(in + 4 * (size_t)i);
    __nv_bfloat16 h0 = __float2bfloat16(v.x);
    __nv_bfloat16 h1 = __float2bfloat16(v.y);
    __nv_bfloat16 h2 = __float2bfloat16(v.z);
    __nv_bfloat16 h3 = __float2bfloat16(v.w);
    __nv_bfloat16 l0 = __float2bfloat16(v.x - __bfloat162float(h0));
    __nv_bfloat16 l1 = __float2bfloat16(v.y - __bfloat162float(h1));
    __nv_bfloat16 l2 = __float2bfloat16(v.z - __bfloat162float(h2));
    __nv_bfloat16 l3 = __float2bfloat16(v.w - __bfloat162float(h3));
    __nv_bfloat162* hp = (__nv_bfloat162*)(hi + 4 * (size_t)i);
    __nv_bfloat162* lp = (__nv_bfloat162*)(lo + 4 * (size_t)i);
    hp[0] = __nv_bfloat162(h0, h1);
    hp[1] = __nv_bfloat162(h2, h3);
    lp[0] = __nv_bfloat162(l0, l1);
    lp[1] = __nv_bfloat162(l2, l3);
}

// ---------------------------------------------------------------------------
// Split-bf16 tensor-core GEMM (mma.sync m16n8k16):
//   C[M,N] = A[M,K] * W[N,K]^T + bias,  A ~ Ah+Al, W ~ Wh+Wl
//   D += Ah*Wh + Ah*Wl + Al*Wh   (fp32 accumulate in registers)
// CTA tile 128x128, BK=32, 8 warps (warp tile 64x32), cp.async double buffer.
// MODE 0: row-major out;  MODE 1: scatter to [B,H,S,dh]
// ---------------------------------------------------------------------------
#define LDT 40                      // bf16 elems per smem row (80B, LDSM conflict-free)
#define T_AH 0
#define T_AL (128 * LDT)
#define T_WH (2 * 128 * LDT)
#define T_WL (3 * 128 * LDT)
#define SSTAGE (4 * 128 * LDT)      // bf16 elems per stage (40960 B)

template <int MODE>
__global__ void __launch_bounds__(256, 2)
gemm_mma(const __nv_bfloat16* __restrict__ Ahi, const __nv_bfloat16* __restrict__ Alo,
         const __nv_bfloat16* __restrict__ Whi, const __nv_bfloat16* __restrict__ Wlo,
         const float* __restrict__ bias, float* __restrict__ C)
{
    constexpr int KD  = EMB;         // 1024
    constexpr int NCH = KD / 32;     // 32 K-chunks

    extern __shared__ __nv_bfloat16 smem[];
    const uint32_t sbase = smem_u32(smem);

    const int tid  = threadIdx.x;
    const int wid  = tid >> 5;
    const int lane = tid & 31;
    const int m0   = blockIdx.y * 128;
    const int n0   = blockIdx.x * 128;

    // global-load mapping: 64 rows/pass, 4x16B per 128-row subtile
    const int glr = tid >> 2;            // 0..63
    const int glc = (tid & 3) * 8;       // bf16 col 0,8,16,24

    auto load_chunk = [&](int c, int stg) {
        const int k0 = c * 32;
        const uint32_t sb = sbase + (uint32_t)stg * (SSTAGE * 2);
#pragma unroll
        for (int p = 0; p < 2; p++) {
            const int row = glr + 64 * p;
            const size_t ga = (size_t)(m0 + row) * KD + k0 + glc;
            const size_t gw = (size_t)(n0 + row) * KD + k0 + glc;
            const uint32_t so = (uint32_t)(row * LDT + glc) * 2;
            cp_async16(sb + T_AH * 2 + so, Ahi + ga);
            cp_async16(sb + T_AL * 2 + so, Alo + ga);
            cp_async16(sb + T_WH * 2 + so, Whi + gw);
            cp_async16(sb + T_WL * 2 + so, Wlo + gw);
        }
    };

    float acc[4][4][4];
#pragma unroll
    for (int i = 0; i < 4; i++)
#pragma unroll
        for (int j = 0; j < 4; j++)
#pragma unroll
            for (int e = 0; e < 4; e++) acc[i][j][e] = 0.f;

    const int wm = wid >> 2;             // 0..1  (M)
    const int wn = wid & 3;              // 0..3  (N)
    const int mbase = wm * 64;
    const int nbase = wn * 32;

    // ldmatrix lane addressing (element offsets, constant parts)
    const int a_row = mbase + (lane & 15);
    const int a_kad = 8 * (lane >> 4);
    const int b_row = nbase + (lane & 7);
    const int b_kad = 8 * ((lane >> 3) & 1);

    load_chunk(0, 0);
    asm volatile("cp.async.commit_group;\n");

    for (int c = 0; c < NCH; c++) {
        if (c + 1 < NCH) {
            load_chunk(c + 1, (c + 1) & 1);
            asm volatile("cp.async.commit_group;\n");
            asm volatile("cp.async.wait_group 1;\n");
        } else {
            asm volatile("cp.async.wait_group 0;\n");
        }
        __syncthreads();

        const uint32_t sb = sbase + (uint32_t)(c & 1) * (SSTAGE * 2);
#pragma unroll
        for (int ks = 0; ks < 2; ks++) {
            const int kk = ks * 16;
            uint32_t ah[4][4], al[4][4];
#pragma unroll
            for (int i = 0; i < 4; i++) {
                const uint32_t ao =
                    (uint32_t)((a_row + i * 16) * LDT + kk + a_kad) * 2;
                ldsm_x4(sb + T_AH * 2 + ao, ah[i]);
                ldsm_x4(sb + T_AL * 2 + ao, al[i]);
            }
#pragma unroll
            for (int j = 0; j < 4; j++) {
                uint32_t bh[2], bl[2];
                const uint32_t bo =
                    (uint32_t)((b_row + j * 8) * LDT + kk + b_kad) * 2;
                ldsm_x2(sb + T_WH * 2 + bo, bh);
                ldsm_x2(sb + T_WL * 2 + bo, bl);
#pragma unroll
                for (int i = 0; i < 4; i++) {
                    mma16816(acc[i][j], ah[i], bh);
                    mma16816(acc[i][j], ah[i], bl);
                    mma16816(acc[i][j], al[i], bh);
                }
            }
        }
        __syncthreads();
    }

    // ---- epilogue ----
    const int qr = lane >> 2;            // 0..7
    const int qc = (lane & 3) * 2;       // 0,2,4,6
#pragma unroll
    for (int i = 0; i < 4; i++) {
#pragma unroll
        for (int j = 0; j < 4; j++) {
            const int n = n0 + nbase + j * 8 + qc;
            const float b0 = bias[n], b1 = bias[n + 1];
#pragma unroll
            for (int half = 0; half < 2; half++) {
                const int m = m0 + mbase + i * 16 + qr + half * 8;
                float2 v;
                v.x = acc[i][j][half * 2 + 0] + b0;
                v.y = acc[i][j][half * 2 + 1] + b1;
                if (MODE == 0) {
                    *(float2*)(C + (size_t)m * EMB + n) = v;
                } else {
                    const int b  = m >> 11;     // SEQ = 2048
                    const int s  = m & 2047;
                    const int h  = n >> 6;      // DH = 64
                    const int d0 = n & 63;
                    *(float2*)(C + (((size_t)(b * NH + h)) * SEQ + s) * DH + d0) = v;
                }
            }
        }
    }
}

// ---------------------------------------------------------------------------
// Banded attention (unchanged from passing R4 kernel)
// ---------------------------------------------------------------------------
__global__ void __launch_bounds__(256, 1)
attn_kernel(const float* __restrict__ Q, const float* __restrict__ K,
            const float* __restrict__ V, float* __restrict__ ctx,
            float* __restrict__ attn, int writeAttn)
{
    constexpr int BQ = 64;
    constexpr int KW = 2 * WIN + BQ;   // 320
    constexpr int PS = KW + 1;         // 321
    constexpr int LD = 68;

    extern __shared__ float smf[];
    float* Qs = smf;
    float* Ts = smf + DH * LD;
    float* Ss = smf + 2 * DH * LD;

    const int tid = threadIdx.x;
    const int tx = tid & 15;
    const int ty = tid >> 4;
    const int qt = blockIdx.x, h = blockIdx.y, b = blockIdx.z;
    const int q0 = qt * BQ;
    const int kstart = q0 - WIN;

    const float* Qb = Q + ((size_t)(b * NH + h) * SEQ + q0) * DH;
    const float* Kb = K + (size_t)(b * NH + h) * SEQ * DH;
    const float* Vb = V + (size_t)(b * NH + h) * SEQ * DH;

#pragma unroll
    for (int i = 0; i < 4; i++) {
        const int idx = tid + i * 256;
        const int row = idx >> 4;
        const int c4 = (idx & 15) << 2;
        float4 v = *(const float4*)(Qb + row * DH + c4);
        Qs[(c4 + 0) * LD + row] = v.x;
        Qs[(c4 + 1) * LD + row] = v.y;
        Qs[(c4 + 2) * LD + row] = v.z;
        Qs[(c4 + 3) * LD + row] = v.w;
    }
    __syncthreads();

    for (int t = 0; t < 5; t++) {
        const int kg0 = kstart + t * 64;
#pragma unroll
        for (int i = 0; i < 4; i++) {
            const int idx = tid + i * 256;
            const int row = idx >> 4;
            const int c4 = (idx & 15) << 2;
            const int kr = kg0 + row;
            float4 v = make_float4(0.f, 0.f, 0.f, 0.f);
            if (kr >= 0 && kr < SEQ)
                v = *(const float4*)(Kb + (size_t)kr * DH + c4);
            Ts[(c4 + 0) * LD + row] = v.x;
            Ts[(c4 + 1) * LD + row] = v.y;
            Ts[(c4 + 2) * LD + row] = v.z;
            Ts[(c4 + 3) * LD + row] = v.w;
        }
        __syncthreads();

        float acc[4][4];
#pragma unroll
        for (int i = 0; i < 4; i++)
#pragma unroll
            for (int j = 0; j < 4; j++) acc[i][j] = 0.f;

#pragma unroll 8
        for (int d = 0; d < DH; d++) {
            float4 av = *(const float4*)&Qs[d * LD + (ty << 2)];
            float4 bv = *(const float4*)&Ts[d * LD + (tx << 2)];
            acc[0][0] += av.x * bv.x; acc[0][1] += av.x * bv.y;
            acc[0][2] += av.x * bv.z; acc[0][3] += av.x * bv.w;
            acc[1][0] += av.y * bv.x; acc[1][1] += av.y * bv.y;
            acc[1][2] += av.y * bv.z; acc[1][3] += av.y * bv.w;
            acc[2][0] += av.z * bv.x; acc[2][1] += av.z * bv.y;
            acc[2][2] += av.z * bv.z; acc[2][3] += av.z * bv.w;
            acc[3][0] += av.w * bv.x; acc[3][1] += av.w * bv.y;
            acc[3][2] += av.w * bv.z; acc[3][3] += av.w * bv.w;
        }
#pragma unroll
        for (int i = 0; i < 4; i++)
#pragma unroll
            for (int j = 0; j < 4; j++)
                Ss[((ty << 2) + i) * PS + t * 64 + (tx << 2) + j] = acc[i][j] * 0.125f;
        __syncthreads();
    }

    const int warp = tid >> 5, lane = tid & 31;
    for (int r = 0; r < 8; r++) {
        const int iq = warp * 8 + r;
        const int q = q0 + iq;
        int jlo = iq;
        if (kstart + jlo < 0) jlo = -kstart;
        int jhi = iq + 2 * WIN;
        if (kstart + jhi > SEQ - 1) jhi = SEQ - 1 - kstart;
        float* row = &Ss[iq * PS];

        for (int j = lane; j < jlo; j += 32) row[j] = 0.f;
        for (int j = jhi + 1 + lane; j < KW; j += 32) row[j] = 0.f;

        float mx = -1e30f;
        for (int j = jlo + lane; j <= jhi; j += 32) mx = fmaxf(mx, row[j]);
#pragma unroll
        for (int o = 16; o; o >>= 1) mx = fmaxf(mx, __shfl_xor_sync(0xffffffffu, mx, o));

        float ssum = 0.f;
        for (int j = jlo + lane; j <= jhi; j += 32) {
            float e = __expf(row[j] - mx);
            row[j] = e;
            ssum += e;
        }
#pragma unroll
        for (int o = 16; o; o >>= 1) ssum += __shfl_xor_sync(0xffffffffu, ssum, o);
        const float inv = 1.f / ssum;

        if (writeAttn) {
            float* arow = attn + ((size_t)(b * NH + h) * SEQ + q) * SEQ;
            for (int j = jlo + lane; j <= jhi; j += 32) {
                float p = row[j] * inv;
                row[j] = p;
                arow[kstart + j] = p;
            }
        } else {
            for (int j = jlo + lane; j <= jhi; j += 32) row[j] *= inv;
        }
    }
    __syncthreads();

    float cacc[4][4];
#pragma unroll
    for (int i = 0; i < 4; i++)
#pragma unroll
        for (int j = 0; j < 4; j++) cacc[i][j] = 0.f;

    for (int t = 0; t < 5; t++) {
        const int kg0 = kstart + t * 64;
#pragma unroll
        for (int i = 0; i < 4; i++) {
            const int idx = tid + i * 256;
            const int row = idx >> 4;
            const int c4 = (idx & 15) << 2;
            const int kr = kg0 + row;
            float4 v = make_float4(0.f, 0.f, 0.f, 0.f);
            if (kr >= 0 && kr < SEQ)
                v = *(const float4*)(Vb + (size_t)kr * DH + c4);
            *(float4*)&Ts[row * LD + c4] = v;
        }
        __syncthreads();

#pragma unroll 8
        for (int kk = 0; kk < 64; kk++) {
            float4 bv = *(const float4*)&Ts[kk * LD + (tx << 2)];
            const int col = t * 64 + kk;
            float a0 = Ss[((ty << 2) + 0) * PS + col];
            float a1 = Ss[((ty << 2) + 1) * PS + col];
            float a2 = Ss[((ty << 2) + 2) * PS + col];
            float a3 = Ss[((ty << 2) + 3) * PS + col];
            cacc[0][0] += a0 * bv.x; cacc[0][1] += a0 * bv.y;
            cacc[0][2] += a0 * bv.z; cacc[0][3] += a0 * bv.w;
            cacc[1][0] += a1 * bv.x; cacc[1][1] += a1 * bv.y;
            cacc[1][2] += a1 * bv.z; cacc[1][3] += a1 * bv.w;
            cacc[2][0] += a2 * bv.x; cacc[2][1] += a2 * bv.y;
            cacc[2][2] += a2 * bv.z; cacc[2][3] += a2 * bv.w;
            cacc[3][0] += a3 * bv.x; cacc[3][1] += a3 * bv.y;
            cacc[3][2] += a3 * bv.z; cacc[3][3] += a3 * bv.w;
        }
        __syncthreads();
    }

#pragma unroll
    for (int i = 0; i < 4; i++) {
        const int q = q0 + (ty << 2) + i;
        float4 val = make_float4(cacc[i][0], cacc[i][1], cacc[i][2], cacc[i][3]);
        *(float4*)(ctx + (((size_t)b * SEQ + q) * NH + h) * DH + (tx << 2)) = val;
    }
}

// ---------------------------------------------------------------------------
extern "C" void kernel_launch(void* const* d_in, const int* in_sizes, int n_in,
                              void* d_out, int out_size)
{
    const float* x  = (const float*)d_in[0];
    const float* Wq = (const float*)d_in[1];
    const float* bq = (const float*)d_in[2];
    const float* Wk = (const float*)d_in[3];
    const float* bk = (const float*)d_in[4];
    const float* Wv = (const float*)d_in[5];
    const float* bv = (const float*)d_in[6];
    const float* Wo = (const float*)d_in[7];
    const float* bo = (const float*)d_in[8];
    float* out = (float*)d_out;

    float *Qp, *Kp, *Vp, *Cp;
    cudaGetSymbolAddress((void**)&Qp, g_Q);
    cudaGetSymbolAddress((void**)&Kp, g_K);
    cudaGetSymbolAddress((void**)&Vp, g_V);
    cudaGetSymbolAddress((void**)&Cp, g_ctx);

    __nv_bfloat16 *xhi, *xlo, *whi, *wlo, *chi, *clo;
    cudaGetSymbolAddress((void**)&xhi, g_xhi);
    cudaGetSymbolAddress((void**)&xlo, g_xlo);
    cudaGetSymbolAddress((void**)&whi, g_whi);
    cudaGetSymbolAddress((void**)&wlo, g_wlo);
    cudaGetSymbolAddress((void**)&chi, g_chi);
    cudaGetSymbolAddress((void**)&clo, g_clo);

    const size_t OUT_ELEMS  = (size_t)BATCH * SEQ * EMB;        // 4,194,304
    const size_t ATTN_ELEMS = (size_t)BATCH * NH * SEQ * SEQ;   // 134,217,728
    const int writeAttn = ((size_t)out_size >= OUT_ELEMS + ATTN_ELEMS) ? 1 : 0;
    float* attn_ptr = out + OUT_ELEMS;

    const int NX = BATCH * SEQ * EMB;   // 4,194,304
    const int NW = EMB * EMB;           // 1,048,576

    // fp32 -> split bf16
    split_bf16<<<NX / 1024, 256>>>(x, xhi, xlo, NX / 4);
    split_bf16<<<NW / 1024, 256>>>(Wq, whi + 0 * (size_t)NW, wlo + 0 * (size_t)NW, NW / 4);
    split_bf16<<<NW / 1024, 256>>>(Wk, whi + 1 * (size_t)NW, wlo + 1 * (size_t)NW, NW / 4);
    split_bf16<<<NW / 1024, 256>>>(Wv, whi + 2 * (size_t)NW, wlo + 2 * (size_t)NW, NW / 4);
    split_bf16<<<NW / 1024, 256>>>(Wo, whi + 3 * (size_t)NW, wlo + 3 * (size_t)NW, NW / 4);

    // mma.sync GEMMs
    constexpr int GSMEM = 2 * SSTAGE * 2;   // 81,920 B
    cudaFuncSetAttribute(gemm_mma<1>, cudaFuncAttributeMaxDynamicSharedMemorySize, GSMEM);
    cudaFuncSetAttribute(gemm_mma<0>, cudaFuncAttributeMaxDynamicSharedMemorySize, GSMEM);

    dim3 ggrid(EMB / 128, (BATCH * SEQ) / 128);   // (8, 32) = 256 CTAs
    gemm_mma<1><<<ggrid, 256, GSMEM>>>(xhi, xlo, whi + 0 * (size_t)NW, wlo + 0 * (size_t)NW, bq, Qp);
    gemm_mma<1><<<ggrid, 256, GSMEM>>>(xhi, xlo, whi + 1 * (size_t)NW, wlo + 1 * (size_t)NW, bk, Kp);
    gemm_mma<1><<<ggrid, 256, GSMEM>>>(xhi, xlo, whi + 2 * (size_t)NW, wlo + 2 * (size_t)NW, bv, Vp);

    // Zero the attn output region (masked entries are exactly 0)
    if (writeAttn)
        cudaMemsetAsync(attn_ptr, 0, ATTN_ELEMS * sizeof(float), 0);

    // Banded attention
    constexpr int SMEM = (2 * 64 * 68 + 64 * 321) * (int)sizeof(float);  // 116,992 B
    cudaFuncSetAttribute(attn_kernel, cudaFuncAttributeMaxDynamicSharedMemorySize, SMEM);
    attn_kernel<<<dim3(SEQ / 64, NH, BATCH), 256, SMEM>>>(Qp, Kp, Vp, Cp, attn_ptr, writeAttn);

    // Output projection
    split_bf16<<<NX / 1024, 256>>>(Cp, chi, clo, NX / 4);
    gemm_mma<0><<<ggrid, 256, GSMEM>>>(chi, clo, whi + 3 * (size_t)NW, wlo + 3 * (size_t)NW, bo, out);
}